// round 16
// baseline (speedup 1.0000x reference)
#include <cuda_runtime.h>
#include <cstdint>

// Problem constants (x = [4096, 8192, 1] f32, G = 7)
constexpr int B_ROWS = 4096;
constexpr int I_COLS = 8192;
constexpr int G      = 7;

constexpr int BT    = 512;   // threads per block, 3 CTAs/SM
constexpr int NW    = 16;    // warps
constexpr int NB    = 768;   // quantile buckets (mean ~10.7)
constexpr int NPAIR = NB / 2;

// ---- dynamic shared memory layout (~60.2 KB -> 3 CTAs/SM) ----
constexpr size_t OFF_DST  = 0;                       // u32 dst[8192]   32768
constexpr size_t OFF_IDC  = 32768;                   // u16 idc[8192]   16384 (b | wide<<15)
constexpr size_t OFF_HIST = OFF_IDC + 16384;         // u32 hist[NB]    3072
constexpr size_t OFF_CUR  = OFF_HIST + NB * 4;       // u32 cur[NB]     3072
constexpr size_t OFF_BASE = OFF_CUR + NB * 4;        // u32 base[NB+1]  3076
constexpr size_t OFF_UX   = OFF_BASE + (NB + 1) * 4; // u32 Ux[NB+1]    3076
constexpr size_t OFF_AUX  = OFF_UX + (NB + 1) * 4;   // u32 aux[16]
constexpr size_t OFF_SCAL = OFF_AUX + 64;            // f32 scal[32]
constexpr size_t SMEM_BYTES = OFF_SCAL + 128;

// key transform: ascending u32 == descending float
__device__ __forceinline__ uint32_t kd(float f) {
    uint32_t b = __float_as_uint(f);
    uint32_t m = (uint32_t)(((int32_t)b) >> 31) | 0x80000000u;
    return ~(b ^ m);
}
__device__ __forceinline__ float inv_kd(uint32_t k) {
    uint32_t u = ~k;
    return __uint_as_float((u & 0x80000000u) ? (u ^ 0x80000000u) : ~u);
}

// bucket of x: MUFU guess from the sigmoid fit of Phi(x), corrected by an
// exact, monotone table walk. Bucket b covers kd range [Ux[b], Ux[b+1]).
__device__ __forceinline__ int bucket_of(float x, uint32_t u, const uint32_t* __restrict__ Ux) {
    float z = fmaf(0.07056f * x * x, x, 1.5976f * x);
    int b = (int)((float)NB * __frcp_rn(1.0f + __expf(z)));   // ~ NB*(1-Phi(x))
    b = max(0, min(NB - 1, b));
    while (b < NB - 1 && u >= Ux[b + 1]) ++b;
    while (b > 0 && u < Ux[b]) --b;
    return b;
}

// ---------------- warp-register bitonic sorts (ascending) ----------------
template <int R>
__device__ __forceinline__ void bitonic32(uint32_t v[R], int lane) {
    constexpr int N = R * 32;
    #pragma unroll
    for (int k = 2; k <= N; k <<= 1) {
        #pragma unroll
        for (int j = k >> 1; j > 0; j >>= 1) {
            if (j >= 32) {
                const int jr = j >> 5;
                #pragma unroll
                for (int r = 0; r < R; r++) {
                    if ((r & jr) == 0) {
                        const int r2 = r + jr;
                        const int e  = r * 32 + lane;
                        const bool up = ((e & k) == 0);
                        uint32_t a = v[r], b = v[r2];
                        uint32_t lo = min(a, b), hi = max(a, b);
                        v[r]  = up ? lo : hi;
                        v[r2] = up ? hi : lo;
                    }
                }
            } else {
                #pragma unroll
                for (int r = 0; r < R; r++) {
                    const int e = r * 32 + lane;
                    uint32_t w = __shfl_xor_sync(0xFFFFFFFFu, v[r], j);
                    const bool up = ((e & k) == 0);
                    const bool keep_lo = (((e & j) == 0) == up);
                    v[r] = keep_lo ? min(v[r], w) : max(v[r], w);
                }
            }
        }
    }
}

template <int R>
__device__ __forceinline__ void bitonic64(unsigned long long v[R], int lane) {
    constexpr int N = R * 32;
    #pragma unroll
    for (int k = 2; k <= N; k <<= 1) {
        #pragma unroll
        for (int j = k >> 1; j > 0; j >>= 1) {
            if (j >= 32) {
                const int jr = j >> 5;
                #pragma unroll
                for (int r = 0; r < R; r++) {
                    if ((r & jr) == 0) {
                        const int r2 = r + jr;
                        const int e  = r * 32 + lane;
                        const bool up = ((e & k) == 0);
                        unsigned long long a = v[r], b = v[r2];
                        unsigned long long lo = a < b ? a : b;
                        unsigned long long hi = a < b ? b : a;
                        v[r]  = up ? lo : hi;
                        v[r2] = up ? hi : lo;
                    }
                }
            } else {
                #pragma unroll
                for (int r = 0; r < R; r++) {
                    const int e = r * 32 + lane;
                    unsigned long long w = __shfl_xor_sync(0xFFFFFFFFu, v[r], j);
                    const bool up = ((e & k) == 0);
                    const bool keep_lo = (((e & j) == 0) == up);
                    v[r] = keep_lo ? (v[r] < w ? v[r] : w) : (v[r] > w ? v[r] : w);
                }
            }
        }
    }
}

__device__ __forceinline__ void emit_packed(
    int gr, uint32_t idx, uint32_t off, uint32_t lo,
    float* __restrict__ si, float* s_top, float* s_bot)
{
    si[gr] = (float)idx;
    if (gr < G || gr >= I_COLS - G) {
        float fv = inv_kd(lo + off);
        if (gr < G) s_top[gr] = fv;
        else        s_bot[gr - (I_COLS - G)] = fv;
    }
}

// ---- 16-wide sub-warp sort: two narrow buckets per warp (payload direct) ----
__device__ __forceinline__ void sort16_u32(
    const uint32_t* __restrict__ dst, int g, int size, uint32_t lo,
    int m, float* __restrict__ si, float* s_top, float* s_bot)
{
    uint32_t v = (m < size) ? dst[g + m] : 0xFFFFFFFFu;
    #pragma unroll
    for (int k = 2; k <= 16; k <<= 1) {
        #pragma unroll
        for (int j = k >> 1; j > 0; j >>= 1) {
            uint32_t w = __shfl_xor_sync(0xFFFFFFFFu, v, j, 16);
            const bool up = ((m & k) == 0);
            const bool keep_lo = (((m & j) == 0) == up);
            v = keep_lo ? min(v, w) : max(v, w);
        }
    }
    if (m < size) emit_packed(g + m, v & 8191u, v >> 13, lo, si, s_top, s_bot);
}

// narrow 32-wide path (offset-packed u32 payload, direct)
template <int R>
__device__ __forceinline__ void sort_bucket_u32(
    const uint32_t* __restrict__ dst, int g, int size, uint32_t lo,
    int lane, float* __restrict__ si, float* s_top, float* s_bot)
{
    uint32_t v[R];
    #pragma unroll
    for (int r = 0; r < R; r++) {
        int m = r * 32 + lane;
        v[r] = (m < size) ? dst[g + m] : 0xFFFFFFFFu;
    }
    bitonic32<R>(v, lane);
    #pragma unroll
    for (int r = 0; r < R; r++) {
        int m = r * 32 + lane;
        if (m < size) emit_packed(g + m, v[r] & 8191u, v[r] >> 13, lo, si, s_top, s_bot);
    }
}

// wide path: dst holds idx; rebuild 45-bit key from x (L1 hits)
template <int R>
__device__ __forceinline__ void sort_bucket_wide(
    const uint32_t* __restrict__ dst, int g, int size,
    const float* __restrict__ xr, int lane,
    float* __restrict__ si, float* s_top, float* s_bot)
{
    unsigned long long v[R];
    #pragma unroll
    for (int r = 0; r < R; r++) {
        int m = r * 32 + lane;
        if (m < size) {
            uint32_t idx = dst[g + m];
            v[r] = ((unsigned long long)kd(xr[idx]) << 13) | idx;
        } else v[r] = ~0ull;
    }
    bitonic64<R>(v, lane);
    #pragma unroll
    for (int r = 0; r < R; r++) {
        int m = r * 32 + lane;
        if (m < size) {
            unsigned long long p = v[r];
            int gr = g + m;
            si[gr] = (float)(unsigned)(p & 8191u);
            if (gr < G)           s_top[gr] = inv_kd((uint32_t)(p >> 13));
            if (gr >= I_COLS - G) s_bot[gr - (I_COLS - G)] = inv_kd((uint32_t)(p >> 13));
        }
    }
}

extern __shared__ unsigned char smem_raw[];

__global__ void __launch_bounds__(BT, 3)
portfolio_bucket_v6(const float* __restrict__ x, float* __restrict__ out)
{
    uint32_t*       dst  = (uint32_t*)(smem_raw + OFF_DST);
    unsigned short* idc  = (unsigned short*)(smem_raw + OFF_IDC);
    uint32_t*       hist = (uint32_t*)(smem_raw + OFF_HIST);
    uint32_t*       cur  = (uint32_t*)(smem_raw + OFF_CUR);
    uint32_t*       base = (uint32_t*)(smem_raw + OFF_BASE);
    uint32_t*       Ux   = (uint32_t*)(smem_raw + OFF_UX);
    uint32_t*       aux  = (uint32_t*)(smem_raw + OFF_AUX);
    float*          s_top = (float*)(smem_raw + OFF_SCAL);   // [7]
    float*          s_bot = s_top + 8;                       // [7]
    float*          s_win = s_top + 16;                      // [7]
    float*          s_los = s_top + 24;                      // [7]

    const int tid  = threadIdx.x;
    const int wid  = tid >> 5;
    const int lane = tid & 31;
    const int row  = blockIdx.x;

    const float*  xr  = x + (size_t)row * I_COLS;
    const float4* xr4 = (const float4*)xr;

    // ---- init: monotone splitter table Ux[0..NB] + zero hist ----
    // Ux[0]=0; Ux[j]=kd(quantile) for 1..NB-1 (ascending); Ux[NB]=max.
    for (int j = tid + 1; j < NB; j += BT) {
        float pj = (float)j * (1.0f / (float)NB);
        float q  = 0.58754f * __logf((1.0f - pj) / pj);
        Ux[j] = kd(q);
    }
    if (tid == 0) { Ux[0] = 0u; Ux[NB] = 0xFFFFFFFFu; base[NB] = I_COLS; }
    for (int i = tid; i < NB; i += BT) hist[i] = 0;
    __syncthreads();

    // ---- Phase 1: bucket each element; cache (b | wide<<15) in idc; hist ----
    #pragma unroll
    for (int q4 = 0; q4 < 4; q4++) {
        int vi = tid + q4 * BT;
        float4 xv = xr4[vi];
        unsigned long long ent = 0;
        #pragma unroll
        for (int c = 0; c < 4; c++) {
            float f = (c == 0) ? xv.x : (c == 1) ? xv.y : (c == 2) ? xv.z : xv.w;
            uint32_t u = kd(f);
            int b = bucket_of(f, u, Ux);
            uint32_t wide = (Ux[b + 1] - Ux[b]) > (1u << 19) ? 0x8000u : 0u;
            ent |= (unsigned long long)((uint32_t)b | wide) << (c * 16);
            atomicAdd(&hist[b], 1u);
        }
        ((unsigned long long*)idc)[vi] = ent;
    }
    __syncthreads();

    // ---- Phase 2: exclusive scan of sizes -> base, cur (hist preserved) ----
    {
        uint32_t c0 = 0, c1 = 0;
        if (tid < NPAIR) { c0 = hist[2 * tid]; c1 = hist[2 * tid + 1]; }
        uint32_t tsum = c0 + c1;
        uint32_t inc = tsum;
        #pragma unroll
        for (int o = 1; o < 32; o <<= 1) {
            uint32_t n = __shfl_up_sync(0xFFFFFFFFu, inc, o);
            if (lane >= o) inc += n;
        }
        if (lane == 31) aux[wid] = inc;
        __syncthreads();
        if (wid == 0) {
            uint32_t v  = (lane < NW) ? aux[lane] : 0;
            uint32_t vi = v;
            #pragma unroll
            for (int o = 1; o < 32; o <<= 1) {
                uint32_t n = __shfl_up_sync(0xFFFFFFFFu, vi, o);
                if (lane >= o) vi += n;
            }
            if (lane < NW) aux[lane] = vi - v;       // exclusive warp prefix
        }
        __syncthreads();
        if (tid < NPAIR) {
            uint32_t excl = aux[wid] + (inc - tsum);
            base[2 * tid] = excl;     cur[2 * tid] = excl;
            base[2 * tid + 1] = excl + c0; cur[2 * tid + 1] = excl + c0;
        }
    }
    __syncthreads();

    // ---- Phase 3: scatter u32 payloads (no id-read barrier: idc separate) ----
    #pragma unroll
    for (int q4 = 0; q4 < 4; q4++) {
        int vi = tid + q4 * BT;
        float4 xv = xr4[vi];                         // L1 re-hit
        unsigned long long w = ((const unsigned long long*)idc)[vi];
        int e = vi * 4;
        #pragma unroll
        for (int c = 0; c < 4; c++) {
            float f = (c == 0) ? xv.x : (c == 1) ? xv.y : (c == 2) ? xv.z : xv.w;
            uint32_t u = kd(f);
            uint32_t b16 = (uint32_t)(w >> (c * 16)) & 0xFFFFu;
            uint32_t b = b16 & 0x7FFFu;
            uint32_t idx = (uint32_t)(e + c);
            uint32_t off = u - Ux[b];
            uint32_t pay = (b16 & 0x8000u) ? idx : ((off << 13) | idx);
            uint32_t pos = atomicAdd(&cur[b], 1u);
            dst[pos] = pay;
        }
    }
    __syncthreads();

    // ---- b_c zero fill (independent; overlaps with sorts) ----
    float* bc = out + (size_t)row * I_COLS;
    float* si = out + (size_t)B_ROWS * I_COLS + (size_t)row * I_COLS;
    {
        float4 z = make_float4(0.f, 0.f, 0.f, 0.f);
        float4* bc4 = (float4*)bc;
        #pragma unroll
        for (int q4 = 0; q4 < 4; q4++) bc4[tid + q4 * BT] = z;
    }

    // ---- Phase 4: two buckets per warp (16-wide nets) where possible ----
    for (int pb = wid; pb < NPAIR; pb += NW) {
        int b0 = 2 * pb, b1 = b0 + 1;
        int s0 = (int)hist[b0], s1 = (int)hist[b1];
        int g0 = (int)base[b0], g1 = (int)base[b1];
        uint32_t lo0 = Ux[b0], mid = Ux[b1], hi1 = Ux[b1 + 1];
        bool nar0 = (mid - lo0) <= (1u << 19);
        bool nar1 = (hi1 - mid) <= (1u << 19);
        if (s0 <= 16 && s1 <= 16 && nar0 && nar1) {
            const int half = lane >> 4, m = lane & 15;
            sort16_u32(dst, half ? g1 : g0, half ? s1 : s0,
                       half ? mid : lo0, m, si, s_top, s_bot);
        } else {
            if (s0 > 0) {
                if (nar0) {
                    if      (s0 <= 32)  sort_bucket_u32<1>(dst, g0, s0, lo0, lane, si, s_top, s_bot);
                    else if (s0 <= 64)  sort_bucket_u32<2>(dst, g0, s0, lo0, lane, si, s_top, s_bot);
                    else if (s0 <= 128) sort_bucket_u32<4>(dst, g0, s0, lo0, lane, si, s_top, s_bot);
                    else goto fb0;
                } else {
                    if      (s0 <= 32)  sort_bucket_wide<1>(dst, g0, s0, xr, lane, si, s_top, s_bot);
                    else if (s0 <= 64)  sort_bucket_wide<2>(dst, g0, s0, xr, lane, si, s_top, s_bot);
                    else if (s0 <= 128) sort_bucket_wide<4>(dst, g0, s0, xr, lane, si, s_top, s_bot);
                    else {
                    fb0:  // unconditional-correctness fallback (statistically unreachable)
                        for (int m = lane; m < s0; m += 32) {
                            uint32_t pm = dst[g0 + m];
                            uint32_t im = nar0 ? (pm & 8191u) : pm;
                            unsigned long long me = ((unsigned long long)kd(xr[im]) << 13) | im;
                            int rank = 0;
                            for (int j = 0; j < s0; j++) {
                                uint32_t pj = dst[g0 + j];
                                uint32_t ij = nar0 ? (pj & 8191u) : pj;
                                unsigned long long kj = ((unsigned long long)kd(xr[ij]) << 13) | ij;
                                rank += (kj < me);
                            }
                            int gr = g0 + rank;
                            si[gr] = (float)im;
                            if (gr < G)           s_top[gr] = xr[im];
                            if (gr >= I_COLS - G) s_bot[gr - (I_COLS - G)] = xr[im];
                        }
                    }
                }
            }
            if (s1 > 0) {
                if (nar1) {
                    if      (s1 <= 32)  sort_bucket_u32<1>(dst, g1, s1, mid, lane, si, s_top, s_bot);
                    else if (s1 <= 64)  sort_bucket_u32<2>(dst, g1, s1, mid, lane, si, s_top, s_bot);
                    else if (s1 <= 128) sort_bucket_u32<4>(dst, g1, s1, mid, lane, si, s_top, s_bot);
                    else goto fb1;
                } else {
                    if      (s1 <= 32)  sort_bucket_wide<1>(dst, g1, s1, xr, lane, si, s_top, s_bot);
                    else if (s1 <= 64)  sort_bucket_wide<2>(dst, g1, s1, xr, lane, si, s_top, s_bot);
                    else if (s1 <= 128) sort_bucket_wide<4>(dst, g1, s1, xr, lane, si, s_top, s_bot);
                    else {
                    fb1:
                        for (int m = lane; m < s1; m += 32) {
                            uint32_t pm = dst[g1 + m];
                            uint32_t im = nar1 ? (pm & 8191u) : pm;
                            unsigned long long me = ((unsigned long long)kd(xr[im]) << 13) | im;
                            int rank = 0;
                            for (int j = 0; j < s1; j++) {
                                uint32_t pj = dst[g1 + j];
                                uint32_t ij = nar1 ? (pj & 8191u) : pj;
                                unsigned long long kj = ((unsigned long long)kd(xr[ij]) << 13) | ij;
                                rank += (kj < me);
                            }
                            int gr = g1 + rank;
                            si[gr] = (float)im;
                            if (gr < G)           s_top[gr] = xr[im];
                            if (gr >= I_COLS - G) s_bot[gr - (I_COLS - G)] = xr[im];
                        }
                    }
                }
            }
        }
    }
    __syncthreads();

    // ---- softmaxes ----
    if (tid == 0) {
        float m = s_top[0];
        #pragma unroll
        for (int i = 1; i < G; i++) m = fmaxf(m, s_top[i]);
        float e[G], s = 0.0f;
        #pragma unroll
        for (int i = 0; i < G; i++) { e[i] = expf(s_top[i] - m); s += e[i]; }
        float inv = 1.0f / s;
        #pragma unroll
        for (int i = 0; i < G; i++) s_win[i] = e[i] * inv;

        float m2 = 1.0f - s_bot[0];
        #pragma unroll
        for (int i = 1; i < G; i++) m2 = fmaxf(m2, 1.0f - s_bot[i]);
        float e2[G], s2 = 0.0f;
        #pragma unroll
        for (int i = 0; i < G; i++) { e2[i] = expf((1.0f - s_bot[i]) - m2); s2 += e2[i]; }
        float inv2 = 1.0f / s2;
        #pragma unroll
        for (int i = 0; i < G; i++) s_los[i] = -e2[i] * inv2;
    }
    __syncthreads();

    if (tid < G)          bc[tid] = s_win[tid];
    else if (tid < 2 * G) bc[I_COLS - G + (tid - G)] = s_los[tid - G];
}

extern "C" void kernel_launch(void* const* d_in, const int* in_sizes, int n_in,
                              void* d_out, int out_size)
{
    (void)in_sizes; (void)n_in; (void)out_size;
    const float* x = (const float*)d_in[0];
    float* out = (float*)d_out;

    cudaFuncSetAttribute(portfolio_bucket_v6,
                         cudaFuncAttributeMaxDynamicSharedMemorySize,
                         (int)SMEM_BYTES);
    portfolio_bucket_v6<<<B_ROWS, BT, SMEM_BYTES>>>(x, out);
}

// round 17
// speedup vs baseline: 1.0505x; 1.0505x over previous
#include <cuda_runtime.h>
#include <cstdint>

// Problem constants (x = [4096, 8192, 1] f32, G = 7)
constexpr int B_ROWS = 4096;
constexpr int I_COLS = 8192;
constexpr int G      = 7;

constexpr int BT    = 512;   // threads per block, 3 CTAs/SM
constexpr int NW    = 16;    // warps
constexpr int NB    = 640;   // quantile buckets (mean ~12.8, proven in R8)
constexpr int NPAIR = NB / 2;

// ---- dynamic shared memory layout (~73.4 KB -> 3 CTAs/SM) ----
constexpr size_t OFF_DST   = 0;                        // u32 dst[8192]     32768
constexpr size_t OFF_CACHE = 32768;                    // u32 cache[8192]   32768 (b|nar<<10|r<<11)
constexpr size_t OFF_HIST  = OFF_CACHE + 32768;        // u32 hist[NB]      2560
constexpr size_t OFF_BASE  = OFF_HIST + NB * 4;        // u32 base[NB+1]    2564
constexpr size_t OFF_UX    = OFF_BASE + (NB + 1) * 4;  // u32 Ux[NB+1]      2564
constexpr size_t OFF_AUX   = OFF_UX + (NB + 1) * 4;    // u32 aux[16]
constexpr size_t OFF_SCAL  = OFF_AUX + 64;             // f32 scal[32]
constexpr size_t SMEM_BYTES = OFF_SCAL + 128;

// key transform: ascending u32 == descending float
__device__ __forceinline__ uint32_t kd(float f) {
    uint32_t b = __float_as_uint(f);
    uint32_t m = (uint32_t)(((int32_t)b) >> 31) | 0x80000000u;
    return ~(b ^ m);
}
__device__ __forceinline__ float inv_kd(uint32_t k) {
    uint32_t u = ~k;
    return __uint_as_float((u & 0x80000000u) ? (u ^ 0x80000000u) : ~u);
}

// bucket of x: MUFU guess from the sigmoid fit of Phi(x), corrected by an
// exact, monotone table walk. Bucket b covers kd range [Ux[b], Ux[b+1]).
__device__ __forceinline__ int bucket_of(float x, uint32_t u, const uint32_t* __restrict__ Ux) {
    float z = fmaf(0.07056f * x * x, x, 1.5976f * x);
    int b = (int)((float)NB * __frcp_rn(1.0f + __expf(z)));   // ~ NB*(1-Phi(x))
    b = max(0, min(NB - 1, b));
    while (b < NB - 1 && u >= Ux[b + 1]) ++b;
    while (b > 0 && u < Ux[b]) --b;
    return b;
}

// ---------------- warp-register bitonic sorts (ascending) ----------------
template <int R>
__device__ __forceinline__ void bitonic32(uint32_t v[R], int lane) {
    constexpr int N = R * 32;
    #pragma unroll
    for (int k = 2; k <= N; k <<= 1) {
        #pragma unroll
        for (int j = k >> 1; j > 0; j >>= 1) {
            if (j >= 32) {
                const int jr = j >> 5;
                #pragma unroll
                for (int r = 0; r < R; r++) {
                    if ((r & jr) == 0) {
                        const int r2 = r + jr;
                        const int e  = r * 32 + lane;
                        const bool up = ((e & k) == 0);
                        uint32_t a = v[r], b = v[r2];
                        uint32_t lo = min(a, b), hi = max(a, b);
                        v[r]  = up ? lo : hi;
                        v[r2] = up ? hi : lo;
                    }
                }
            } else {
                #pragma unroll
                for (int r = 0; r < R; r++) {
                    const int e = r * 32 + lane;
                    uint32_t w = __shfl_xor_sync(0xFFFFFFFFu, v[r], j);
                    const bool up = ((e & k) == 0);
                    const bool keep_lo = (((e & j) == 0) == up);
                    v[r] = keep_lo ? min(v[r], w) : max(v[r], w);
                }
            }
        }
    }
}

template <int R>
__device__ __forceinline__ void bitonic64(unsigned long long v[R], int lane) {
    constexpr int N = R * 32;
    #pragma unroll
    for (int k = 2; k <= N; k <<= 1) {
        #pragma unroll
        for (int j = k >> 1; j > 0; j >>= 1) {
            if (j >= 32) {
                const int jr = j >> 5;
                #pragma unroll
                for (int r = 0; r < R; r++) {
                    if ((r & jr) == 0) {
                        const int r2 = r + jr;
                        const int e  = r * 32 + lane;
                        const bool up = ((e & k) == 0);
                        unsigned long long a = v[r], b = v[r2];
                        unsigned long long lo = a < b ? a : b;
                        unsigned long long hi = a < b ? b : a;
                        v[r]  = up ? lo : hi;
                        v[r2] = up ? hi : lo;
                    }
                }
            } else {
                #pragma unroll
                for (int r = 0; r < R; r++) {
                    const int e = r * 32 + lane;
                    unsigned long long w = __shfl_xor_sync(0xFFFFFFFFu, v[r], j);
                    const bool up = ((e & k) == 0);
                    const bool keep_lo = (((e & j) == 0) == up);
                    v[r] = keep_lo ? (v[r] < w ? v[r] : w) : (v[r] > w ? v[r] : w);
                }
            }
        }
    }
}

__device__ __forceinline__ void emit_packed(
    int gr, uint32_t idx, uint32_t off, uint32_t lo,
    float* __restrict__ si, float* s_top, float* s_bot)
{
    si[gr] = (float)idx;
    if (gr < G || gr >= I_COLS - G) {
        float fv = inv_kd(lo + off);
        if (gr < G) s_top[gr] = fv;
        else        s_bot[gr - (I_COLS - G)] = fv;
    }
}

// ---- 16-wide sub-warp sort: two narrow buckets per warp (payload direct) ----
__device__ __forceinline__ void sort16_u32(
    const uint32_t* __restrict__ dst, int g, int size, uint32_t lo,
    int m, float* __restrict__ si, float* s_top, float* s_bot)
{
    uint32_t v = (m < size) ? dst[g + m] : 0xFFFFFFFFu;
    #pragma unroll
    for (int k = 2; k <= 16; k <<= 1) {
        #pragma unroll
        for (int j = k >> 1; j > 0; j >>= 1) {
            uint32_t w = __shfl_xor_sync(0xFFFFFFFFu, v, j, 16);
            const bool up = ((m & k) == 0);
            const bool keep_lo = (((m & j) == 0) == up);
            v = keep_lo ? min(v, w) : max(v, w);
        }
    }
    if (m < size) emit_packed(g + m, v & 8191u, v >> 13, lo, si, s_top, s_bot);
}

// narrow 32-wide path (offset-packed u32 payload, direct)
template <int R>
__device__ __forceinline__ void sort_bucket_u32(
    const uint32_t* __restrict__ dst, int g, int size, uint32_t lo,
    int lane, float* __restrict__ si, float* s_top, float* s_bot)
{
    uint32_t v[R];
    #pragma unroll
    for (int r = 0; r < R; r++) {
        int m = r * 32 + lane;
        v[r] = (m < size) ? dst[g + m] : 0xFFFFFFFFu;
    }
    bitonic32<R>(v, lane);
    #pragma unroll
    for (int r = 0; r < R; r++) {
        int m = r * 32 + lane;
        if (m < size) emit_packed(g + m, v[r] & 8191u, v[r] >> 13, lo, si, s_top, s_bot);
    }
}

// wide path: dst holds idx; rebuild 45-bit key from x (L1 hits)
template <int R>
__device__ __forceinline__ void sort_bucket_wide(
    const uint32_t* __restrict__ dst, int g, int size,
    const float* __restrict__ xr, int lane,
    float* __restrict__ si, float* s_top, float* s_bot)
{
    unsigned long long v[R];
    #pragma unroll
    for (int r = 0; r < R; r++) {
        int m = r * 32 + lane;
        if (m < size) {
            uint32_t idx = dst[g + m];
            v[r] = ((unsigned long long)kd(xr[idx]) << 13) | idx;
        } else v[r] = ~0ull;
    }
    bitonic64<R>(v, lane);
    #pragma unroll
    for (int r = 0; r < R; r++) {
        int m = r * 32 + lane;
        if (m < size) {
            unsigned long long p = v[r];
            int gr = g + m;
            si[gr] = (float)(unsigned)(p & 8191u);
            if (gr < G)           s_top[gr] = inv_kd((uint32_t)(p >> 13));
            if (gr >= I_COLS - G) s_bot[gr - (I_COLS - G)] = inv_kd((uint32_t)(p >> 13));
        }
    }
}

extern __shared__ unsigned char smem_raw[];

__global__ void __launch_bounds__(BT, 3)
portfolio_bucket_v7(const float* __restrict__ x, float* __restrict__ out)
{
    uint32_t* dst   = (uint32_t*)(smem_raw + OFF_DST);
    uint32_t* cache = (uint32_t*)(smem_raw + OFF_CACHE);
    uint32_t* hist  = (uint32_t*)(smem_raw + OFF_HIST);
    uint32_t* base  = (uint32_t*)(smem_raw + OFF_BASE);
    uint32_t* Ux    = (uint32_t*)(smem_raw + OFF_UX);
    uint32_t* aux   = (uint32_t*)(smem_raw + OFF_AUX);
    float*    s_top = (float*)(smem_raw + OFF_SCAL);   // [7]
    float*    s_bot = s_top + 8;                       // [7]
    float*    s_win = s_top + 16;                      // [7]
    float*    s_los = s_top + 24;                      // [7]

    const int tid  = threadIdx.x;
    const int wid  = tid >> 5;
    const int lane = tid & 31;
    const int row  = blockIdx.x;

    const float*  xr  = x + (size_t)row * I_COLS;
    const float4* xr4 = (const float4*)xr;

    // ---- init: monotone splitter table Ux[0..NB] + zero hist ----
    for (int j = tid + 1; j < NB; j += BT) {
        float pj = (float)j * (1.0f / (float)NB);
        float q  = 0.58754f * __logf((1.0f - pj) / pj);
        Ux[j] = kd(q);
    }
    if (tid == 0) { Ux[0] = 0u; Ux[NB] = 0xFFFFFFFFu; base[NB] = I_COLS; }
    for (int i = tid; i < NB; i += BT) hist[i] = 0;
    __syncthreads();

    // ---- Phase 1: bucket + rank from the SAME atomic; cache (b|nar|r) ----
    // The atomic's return value is a unique within-bucket rank. Within-bucket
    // order is arbitrary; the Phase-4 sort restores exact (key, idx) order,
    // so stability (ties -> index ascending) is preserved via idx in payload.
    #pragma unroll
    for (int q4 = 0; q4 < 4; q4++) {
        int vi = tid + q4 * BT;
        float4 xv = xr4[vi];
        uint32_t cc[4];
        #pragma unroll
        for (int c = 0; c < 4; c++) {
            float f = (c == 0) ? xv.x : (c == 1) ? xv.y : (c == 2) ? xv.z : xv.w;
            uint32_t u = kd(f);
            int b = bucket_of(f, u, Ux);
            uint32_t nar = (Ux[b + 1] - Ux[b]) <= (1u << 19) ? (1u << 10) : 0u;
            uint32_t r = atomicAdd(&hist[b], 1u);
            cc[c] = (uint32_t)b | nar | (r << 11);
        }
        ((uint4*)cache)[vi] = make_uint4(cc[0], cc[1], cc[2], cc[3]);
    }
    __syncthreads();

    // ---- Phase 2: exclusive scan of sizes -> base (hist preserved) ----
    {
        uint32_t c0 = 0, c1 = 0;
        if (tid < NPAIR) { c0 = hist[2 * tid]; c1 = hist[2 * tid + 1]; }
        uint32_t tsum = c0 + c1;
        uint32_t inc = tsum;
        #pragma unroll
        for (int o = 1; o < 32; o <<= 1) {
            uint32_t n = __shfl_up_sync(0xFFFFFFFFu, inc, o);
            if (lane >= o) inc += n;
        }
        if (lane == 31) aux[wid] = inc;
        __syncthreads();
        if (wid == 0) {
            uint32_t v  = (lane < NW) ? aux[lane] : 0;
            uint32_t vi = v;
            #pragma unroll
            for (int o = 1; o < 32; o <<= 1) {
                uint32_t n = __shfl_up_sync(0xFFFFFFFFu, vi, o);
                if (lane >= o) vi += n;
            }
            if (lane < NW) aux[lane] = vi - v;       // exclusive warp prefix
        }
        __syncthreads();
        if (tid < NPAIR) {
            uint32_t excl = aux[wid] + (inc - tsum);
            base[2 * tid] = excl;
            base[2 * tid + 1] = excl + c0;
        }
    }
    __syncthreads();

    // ---- Phase 3: ATOMIC-FREE scatter: pos = base[b] + r ----
    #pragma unroll
    for (int q4 = 0; q4 < 4; q4++) {
        int vi = tid + q4 * BT;
        float4 xv = xr4[vi];                         // L1 re-hit
        uint4 cc = ((const uint4*)cache)[vi];
        int e = vi * 4;
        #pragma unroll
        for (int c = 0; c < 4; c++) {
            float f = (c == 0) ? xv.x : (c == 1) ? xv.y : (c == 2) ? xv.z : xv.w;
            uint32_t cw = (c == 0) ? cc.x : (c == 1) ? cc.y : (c == 2) ? cc.z : cc.w;
            uint32_t u = kd(f);
            uint32_t b = cw & 1023u;
            uint32_t r = cw >> 11;
            uint32_t idx = (uint32_t)(e + c);
            uint32_t off = u - Ux[b];
            uint32_t pay = (cw & (1u << 10)) ? ((off << 13) | idx) : idx;
            dst[base[b] + r] = pay;
        }
    }
    __syncthreads();

    // ---- b_c zero fill (independent; overlaps with sorts) ----
    float* bc = out + (size_t)row * I_COLS;
    float* si = out + (size_t)B_ROWS * I_COLS + (size_t)row * I_COLS;
    {
        float4 z = make_float4(0.f, 0.f, 0.f, 0.f);
        float4* bc4 = (float4*)bc;
        #pragma unroll
        for (int q4 = 0; q4 < 4; q4++) bc4[tid + q4 * BT] = z;
    }

    // ---- Phase 4: two buckets per warp (16-wide nets) where possible ----
    for (int pb = wid; pb < NPAIR; pb += NW) {
        int b0 = 2 * pb, b1 = b0 + 1;
        int s0 = (int)hist[b0], s1 = (int)hist[b1];
        int g0 = (int)base[b0], g1 = (int)base[b1];
        uint32_t lo0 = Ux[b0], mid = Ux[b1], hi1 = Ux[b1 + 1];
        bool nar0 = (mid - lo0) <= (1u << 19);
        bool nar1 = (hi1 - mid) <= (1u << 19);
        if (s0 <= 16 && s1 <= 16 && nar0 && nar1) {
            const int half = lane >> 4, m = lane & 15;
            sort16_u32(dst, half ? g1 : g0, half ? s1 : s0,
                       half ? mid : lo0, m, si, s_top, s_bot);
        } else {
            if (s0 > 0) {
                if (nar0) {
                    if      (s0 <= 32)  sort_bucket_u32<1>(dst, g0, s0, lo0, lane, si, s_top, s_bot);
                    else if (s0 <= 64)  sort_bucket_u32<2>(dst, g0, s0, lo0, lane, si, s_top, s_bot);
                    else if (s0 <= 128) sort_bucket_u32<4>(dst, g0, s0, lo0, lane, si, s_top, s_bot);
                    else goto fb0;
                } else {
                    if      (s0 <= 32)  sort_bucket_wide<1>(dst, g0, s0, xr, lane, si, s_top, s_bot);
                    else if (s0 <= 64)  sort_bucket_wide<2>(dst, g0, s0, xr, lane, si, s_top, s_bot);
                    else if (s0 <= 128) sort_bucket_wide<4>(dst, g0, s0, xr, lane, si, s_top, s_bot);
                    else {
                    fb0:  // unconditional-correctness fallback (statistically unreachable)
                        for (int m = lane; m < s0; m += 32) {
                            uint32_t pm = dst[g0 + m];
                            uint32_t im = nar0 ? (pm & 8191u) : pm;
                            unsigned long long me = ((unsigned long long)kd(xr[im]) << 13) | im;
                            int rank = 0;
                            for (int j = 0; j < s0; j++) {
                                uint32_t pj = dst[g0 + j];
                                uint32_t ij = nar0 ? (pj & 8191u) : pj;
                                unsigned long long kj = ((unsigned long long)kd(xr[ij]) << 13) | ij;
                                rank += (kj < me);
                            }
                            int gr = g0 + rank;
                            si[gr] = (float)im;
                            if (gr < G)           s_top[gr] = xr[im];
                            if (gr >= I_COLS - G) s_bot[gr - (I_COLS - G)] = xr[im];
                        }
                    }
                }
            }
            if (s1 > 0) {
                if (nar1) {
                    if      (s1 <= 32)  sort_bucket_u32<1>(dst, g1, s1, mid, lane, si, s_top, s_bot);
                    else if (s1 <= 64)  sort_bucket_u32<2>(dst, g1, s1, mid, lane, si, s_top, s_bot);
                    else if (s1 <= 128) sort_bucket_u32<4>(dst, g1, s1, mid, lane, si, s_top, s_bot);
                    else goto fb1;
                } else {
                    if      (s1 <= 32)  sort_bucket_wide<1>(dst, g1, s1, xr, lane, si, s_top, s_bot);
                    else if (s1 <= 64)  sort_bucket_wide<2>(dst, g1, s1, xr, lane, si, s_top, s_bot);
                    else if (s1 <= 128) sort_bucket_wide<4>(dst, g1, s1, xr, lane, si, s_top, s_bot);
                    else {
                    fb1:
                        for (int m = lane; m < s1; m += 32) {
                            uint32_t pm = dst[g1 + m];
                            uint32_t im = nar1 ? (pm & 8191u) : pm;
                            unsigned long long me = ((unsigned long long)kd(xr[im]) << 13) | im;
                            int rank = 0;
                            for (int j = 0; j < s1; j++) {
                                uint32_t pj = dst[g1 + j];
                                uint32_t ij = nar1 ? (pj & 8191u) : pj;
                                unsigned long long kj = ((unsigned long long)kd(xr[ij]) << 13) | ij;
                                rank += (kj < me);
                            }
                            int gr = g1 + rank;
                            si[gr] = (float)im;
                            if (gr < G)           s_top[gr] = xr[im];
                            if (gr >= I_COLS - G) s_bot[gr - (I_COLS - G)] = xr[im];
                        }
                    }
                }
            }
        }
    }
    __syncthreads();

    // ---- softmaxes ----
    if (tid == 0) {
        float m = s_top[0];
        #pragma unroll
        for (int i = 1; i < G; i++) m = fmaxf(m, s_top[i]);
        float e[G], s = 0.0f;
        #pragma unroll
        for (int i = 0; i < G; i++) { e[i] = expf(s_top[i] - m); s += e[i]; }
        float inv = 1.0f / s;
        #pragma unroll
        for (int i = 0; i < G; i++) s_win[i] = e[i] * inv;

        float m2 = 1.0f - s_bot[0];
        #pragma unroll
        for (int i = 1; i < G; i++) m2 = fmaxf(m2, 1.0f - s_bot[i]);
        float e2[G], s2 = 0.0f;
        #pragma unroll
        for (int i = 0; i < G; i++) { e2[i] = expf((1.0f - s_bot[i]) - m2); s2 += e2[i]; }
        float inv2 = 1.0f / s2;
        #pragma unroll
        for (int i = 0; i < G; i++) s_los[i] = -e2[i] * inv2;
    }
    __syncthreads();

    if (tid < G)          bc[tid] = s_win[tid];
    else if (tid < 2 * G) bc[I_COLS - G + (tid - G)] = s_los[tid - G];
}

extern "C" void kernel_launch(void* const* d_in, const int* in_sizes, int n_in,
                              void* d_out, int out_size)
{
    (void)in_sizes; (void)n_in; (void)out_size;
    const float* x = (const float*)d_in[0];
    float* out = (float*)d_out;

    cudaFuncSetAttribute(portfolio_bucket_v7,
                         cudaFuncAttributeMaxDynamicSharedMemorySize,
                         (int)SMEM_BYTES);
    portfolio_bucket_v7<<<B_ROWS, BT, SMEM_BYTES>>>(x, out);
}